// round 11
// baseline (speedup 1.0000x reference)
#include <cuda_runtime.h>
#include <cuda_bf16.h>

#define THREADS 256
#define PSTRIDE 33       // float2 row stride of P: bankpair(c*33+r) = (c+r)%16
#define GRID 888         // 6 CTAs/SM x 148 SMs -> whole grid resident at once

__device__ __forceinline__ float pick4(const float4& v, int e) {
    return (e == 0) ? v.x : (e == 1) ? v.y : (e == 2) ? v.z : v.w;
}

__global__ __launch_bounds__(THREADS, 6)
void sym_equiv_kernel(const float* __restrict__ X,
                      const float* __restrict__ w,
                      float* __restrict__ out)
{
    // P[c][r] = (X[r][c], X[r+32][c]),  c in [0,64), r in [0,32)
    __shared__ float2 P[64 * PSTRIDE];          // 16,896 B
    __shared__ float Cvec[64];
    __shared__ __align__(16) float Tw[8];
    __shared__ __align__(16) float Dw[8];
    __shared__ float ws[15];

    const int t  = threadIdx.x;
    const int i1 = t >> 3;              // owns rows i1 and i1+32  (i1 in 0..31)
    const int q  = t & 7;
    const int ib = q << 2;              // owns cols [ib,ib+4) and [ib+32,ib+36)

    if (t < 15) ws[t] = w[t];

    #pragma unroll 1
    for (int b = blockIdx.x; b < 1024; b += GRID) {
        // ---- Phase 1: 4 coalesced float4 loads; 8 paired STS.64;
        //      r1 (width-8), diag from regs, T/D warp partials (2-SHFL trick).
        const float* base = X + (size_t)b * 4096;
        float4 va0 = *(const float4*)(base + i1 * 64 + ib);
        float4 va1 = *(const float4*)(base + i1 * 64 + ib + 32);
        float4 vb0 = *(const float4*)(base + (i1 + 32) * 64 + ib);
        float4 vb1 = *(const float4*)(base + (i1 + 32) * 64 + ib + 32);

        {
            float2* p0 = P + (size_t)ib * PSTRIDE + i1;          // cols ib..ib+3
            float2* p1 = P + (size_t)(ib + 32) * PSTRIDE + i1;   // cols ib+32..+35
            p0[0*PSTRIDE] = make_float2(va0.x, vb0.x);
            p0[1*PSTRIDE] = make_float2(va0.y, vb0.y);
            p0[2*PSTRIDE] = make_float2(va0.z, vb0.z);
            p0[3*PSTRIDE] = make_float2(va0.w, vb0.w);
            p1[0*PSTRIDE] = make_float2(va1.x, vb1.x);
            p1[1*PSTRIDE] = make_float2(va1.y, vb1.y);
            p1[2*PSTRIDE] = make_float2(va1.z, vb1.z);
            p1[3*PSTRIDE] = make_float2(va1.w, vb1.w);
        }

        // diagonals from registers: X[i1][i1] lives in octet lane (i1>>2),
        // low half (va0); X[i1+32][i1+32] in the same lane's high half (vb1).
        const int dlane = i1 >> 2;
        const float xa = __shfl_sync(0xffffffffu, pick4(va0, i1 & 3), dlane, 8);
        const float xb = __shfl_sync(0xffffffffu, pick4(vb1, i1 & 3), dlane, 8);

        const float pa = (va0.x + va0.y + va0.z + va0.w) + (va1.x + va1.y + va1.z + va1.w);
        const float pb = (vb0.x + vb0.y + vb0.z + vb0.w) + (vb1.x + vb1.y + vb1.z + vb1.w);
        float r1a = pa, r1b = pb;
        r1a += __shfl_xor_sync(0xffffffffu, r1a, 1, 8);
        r1a += __shfl_xor_sync(0xffffffffu, r1a, 2, 8);
        r1a += __shfl_xor_sync(0xffffffffu, r1a, 4, 8);
        r1b += __shfl_xor_sync(0xffffffffu, r1b, 1, 8);
        r1b += __shfl_xor_sync(0xffffffffu, r1b, 2, 8);
        r1b += __shfl_xor_sync(0xffffffffu, r1b, 4, 8);

        // r1a+r1b and xa+xb are octet-uniform -> warp sum needs only xor 8,16.
        float s = r1a + r1b;
        s += __shfl_xor_sync(0xffffffffu, s, 8);
        s += __shfl_xor_sync(0xffffffffu, s, 16);
        float d = xa + xb;
        d += __shfl_xor_sync(0xffffffffu, d, 8);
        d += __shfl_xor_sync(0xffffffffu, d, 16);
        if ((t & 31) == 0) { Tw[t >> 5] = s; Dw[t >> 5] = d; }

        __syncthreads();                    // (1) P, Tw, Dw ready

        // ---- Phase 2: 8 LDS.64 transpose reads, fused with the
        //      w8*X + w6*X^T fold and the column-sum (r2) partials.
        const float w8v = ws[8], w6v = ws[6];
        float r2a, r2b;
        {
            const float2* pa0 = P + (size_t)i1 * PSTRIDE + ib;        // col i1
            const float2* pb0 = P + (size_t)(i1 + 32) * PSTRIDE + ib; // col i1+32
            float2 q0 = pa0[0], q1 = pa0[1], q2 = pa0[2], q3 = pa0[3];
            r2a = ((q0.x + q1.x) + (q2.x + q3.x)) + ((q0.y + q1.y) + (q2.y + q3.y));
            va0.x = w8v*va0.x + w6v*q0.x;  va1.x = w8v*va1.x + w6v*q0.y;
            va0.y = w8v*va0.y + w6v*q1.x;  va1.y = w8v*va1.y + w6v*q1.y;
            va0.z = w8v*va0.z + w6v*q2.x;  va1.z = w8v*va1.z + w6v*q2.y;
            va0.w = w8v*va0.w + w6v*q3.x;  va1.w = w8v*va1.w + w6v*q3.y;
            q0 = pb0[0]; q1 = pb0[1]; q2 = pb0[2]; q3 = pb0[3];
            r2b = ((q0.x + q1.x) + (q2.x + q3.x)) + ((q0.y + q1.y) + (q2.y + q3.y));
            vb0.x = w8v*vb0.x + w6v*q0.x;  vb1.x = w8v*vb1.x + w6v*q0.y;
            vb0.y = w8v*vb0.y + w6v*q1.x;  vb1.y = w8v*vb1.y + w6v*q1.y;
            vb0.z = w8v*vb0.z + w6v*q2.x;  vb1.z = w8v*vb1.z + w6v*q2.y;
            vb0.w = w8v*vb0.w + w6v*q3.x;  vb1.w = w8v*vb1.w + w6v*q3.y;
        }
        // 8 row-mates' chunks tile all 64 rows -> width-8 reduce = full column sums
        r2a += __shfl_xor_sync(0xffffffffu, r2a, 1, 8);
        r2a += __shfl_xor_sync(0xffffffffu, r2a, 2, 8);
        r2a += __shfl_xor_sync(0xffffffffu, r2a, 4, 8);
        r2b += __shfl_xor_sync(0xffffffffu, r2b, 1, 8);
        r2b += __shfl_xor_sync(0xffffffffu, r2b, 2, 8);
        r2b += __shfl_xor_sync(0xffffffffu, r2b, 4, 8);

        // weight folding (partition map from _set_partitions([0,1,2,3]) order)
        const float aA  = ws[12]*r1a + ws[13]*r2a + ws[3]*xa;     // row i1
        const float eA  = ws[5] *r1a + ws[9] *r2a + ws[0]*xa;
        const float aB  = ws[12]*r1b + ws[13]*r2b + ws[3]*xb;     // row i1+32
        const float eB  = ws[5] *r1b + ws[9] *r2b + ws[0]*xb;
        if (q == 0) {
            Cvec[i1]      = ws[7]*r1a + ws[10]*r2a + ws[1]*xa;
            Cvec[i1 + 32] = ws[7]*r1b + ws[10]*r2b + ws[1]*xb;
        }

        __syncthreads();                    // (2) Cvec ready

        // ---- Phase 3: close with T, D (float4 reads); emit 16 outputs.
        float T, D;
        {
            const float4 t0 = *(const float4*)Tw, t1 = *(const float4*)(Tw + 4);
            const float4 d0 = *(const float4*)Dw, d1 = *(const float4*)(Dw + 4);
            T = ((t0.x + t0.y) + (t0.z + t0.w)) + ((t1.x + t1.y) + (t1.z + t1.w));
            D = ((d0.x + d0.y) + (d0.z + d0.w)) + ((d1.x + d1.y) + (d1.z + d1.w));
        }
        const float gT = ws[14]*T + ws[4]*D;       // constant part
        const float gE = ws[11]*T + ws[2]*D;       // diagonal constant part
        const float cA = aA + gT, cB = aB + gT;
        const float evA = eA + gE, evB = eB + gE;

        const float4 c0 = *(const float4*)(Cvec + ib);
        const float4 c1 = *(const float4*)(Cvec + ib + 32);

        float4 oA0, oA1, oB0, oB1;
        oA0.x = cA + c0.x + va0.x;  oA0.y = cA + c0.y + va0.y;
        oA0.z = cA + c0.z + va0.z;  oA0.w = cA + c0.w + va0.w;
        oA1.x = cA + c1.x + va1.x;  oA1.y = cA + c1.y + va1.y;
        oA1.z = cA + c1.z + va1.z;  oA1.w = cA + c1.w + va1.w;
        oB0.x = cB + c0.x + vb0.x;  oB0.y = cB + c0.y + vb0.y;
        oB0.z = cB + c0.z + vb0.z;  oB0.w = cB + c0.w + vb0.w;
        oB1.x = cB + c1.x + vb1.x;  oB1.y = cB + c1.y + vb1.y;
        oB1.z = cB + c1.z + vb1.z;  oB1.w = cB + c1.w + vb1.w;

        // diagonal corrections: row i1 diag col i1 (low half); row i1+32 diag
        // col i1+32 (high half). Both land in the thread with ib == (i1 & ~3).
        const int dd = i1 - ib;
        if (dd >= 0 && dd < 4) {
            (&oA0.x)[dd] += evA;
            (&oB1.x)[dd] += evB;
        }

        float* orow = out + (size_t)b * 4096;
        *(float4*)(orow + i1 * 64 + ib)             = oA0;
        *(float4*)(orow + i1 * 64 + ib + 32)        = oA1;
        *(float4*)(orow + (i1 + 32) * 64 + ib)      = oB0;
        *(float4*)(orow + (i1 + 32) * 64 + ib + 32) = oB1;

        if (b + GRID < 1024) __syncthreads();   // protect P reuse (uniform cond)
    }
}

extern "C" void kernel_launch(void* const* d_in, const int* in_sizes, int n_in,
                              void* d_out, int out_size)
{
    const float* X = (const float*)d_in[0];      // (1024, 4096) fp32
    const float* w = (const float*)d_in[1];      // (15,) fp32
    // d_in[2] = B (15,4096,4096) — unused: W is fully determined by w via the
    // partition-structure decomposition (validated R0-R9, rel_err ~4e-7).
    float* out = (float*)d_out;                  // (1024, 4096) fp32
    (void)in_sizes; (void)n_in; (void)out_size;

    sym_equiv_kernel<<<GRID, THREADS>>>(X, w, out);
}

// round 13
// speedup vs baseline: 1.1910x; 1.1910x over previous
#include <cuda_runtime.h>
#include <cuda_bf16.h>

#define THREADS 256
#define PSTRIDE 33       // float2 row stride of P: bankpair(c*33+r) = (c+r)%16

__device__ __forceinline__ float pick4(const float4& v, int e) {
    return (e == 0) ? v.x : (e == 1) ? v.y : (e == 2) ? v.z : v.w;
}

__global__ __launch_bounds__(THREADS, 6)
void sym_equiv_kernel(const float* __restrict__ X,
                      const float* __restrict__ w,
                      float* __restrict__ out)
{
    // P[c][r] = (X[r][c], X[r+32][c]),  c in [0,64), r in [0,32)
    __shared__ float2 P[64 * PSTRIDE];          // 16,896 B
    __shared__ float Cvec[64];
    __shared__ __align__(16) float Tw[8];
    __shared__ __align__(16) float Dw[8];
    __shared__ float ws[15];

    const int t  = threadIdx.x;
    const int b  = blockIdx.x;
    const int i1 = t >> 3;              // owns rows i1 and i1+32  (i1 in 0..31)
    const int q  = t & 7;
    const int ib = q << 2;              // owns cols [ib,ib+4) and [ib+32,ib+36)

    if (t < 15) ws[t] = w[t];

    // ---- Phase 1: 4 coalesced float4 loads; 8 paired STS.64; r1/T/D reductions.
    const float* base = X + (size_t)b * 4096;
    float4 va0 = *(const float4*)(base + i1 * 64 + ib);
    float4 va1 = *(const float4*)(base + i1 * 64 + ib + 32);
    float4 vb0 = *(const float4*)(base + (i1 + 32) * 64 + ib);
    float4 vb1 = *(const float4*)(base + (i1 + 32) * 64 + ib + 32);

    {
        float2* p0 = P + (size_t)ib * PSTRIDE + i1;          // cols ib..ib+3
        float2* p1 = P + (size_t)(ib + 32) * PSTRIDE + i1;   // cols ib+32..+35
        p0[0*PSTRIDE] = make_float2(va0.x, vb0.x);
        p0[1*PSTRIDE] = make_float2(va0.y, vb0.y);
        p0[2*PSTRIDE] = make_float2(va0.z, vb0.z);
        p0[3*PSTRIDE] = make_float2(va0.w, vb0.w);
        p1[0*PSTRIDE] = make_float2(va1.x, vb1.x);
        p1[1*PSTRIDE] = make_float2(va1.y, vb1.y);
        p1[2*PSTRIDE] = make_float2(va1.z, vb1.z);
        p1[3*PSTRIDE] = make_float2(va1.w, vb1.w);
    }

    // diagonals from registers: X[i1][i1] lives in lane (i1>>2) of this octet,
    // low half (va0); X[i1+32][i1+32] in the same lane's high half (vb1).
    const int dq_own = i1 >> 2;
    const float xa = __shfl_sync(0xffffffffu, pick4(va0, i1 & 3), dq_own, 8);
    const float xb = __shfl_sync(0xffffffffu, pick4(vb1, i1 & 3), dq_own, 8);

    const float pa = (va0.x + va0.y + va0.z + va0.w) + (va1.x + va1.y + va1.z + va1.w);
    const float pb = (vb0.x + vb0.y + vb0.z + vb0.w) + (vb1.x + vb1.y + vb1.z + vb1.w);
    float r1a = pa, r1b = pb;
    r1a += __shfl_xor_sync(0xffffffffu, r1a, 1, 8);
    r1a += __shfl_xor_sync(0xffffffffu, r1a, 2, 8);
    r1a += __shfl_xor_sync(0xffffffffu, r1a, 4, 8);
    r1b += __shfl_xor_sync(0xffffffffu, r1b, 1, 8);
    r1b += __shfl_xor_sync(0xffffffffu, r1b, 2, 8);
    r1b += __shfl_xor_sync(0xffffffffu, r1b, 4, 8);

    float ps = pa + pb;
    float dq = (q == 0) ? (xa + xb) : 0.f;
    #pragma unroll
    for (int o = 16; o > 0; o >>= 1) {
        ps += __shfl_xor_sync(0xffffffffu, ps, o);
        dq += __shfl_xor_sync(0xffffffffu, dq, o);
    }
    if ((t & 31) == 0) { Tw[t >> 5] = ps; Dw[t >> 5] = dq; }

    __syncthreads();                    // (1) P, Tw, Dw ready

    // ---- Phase 2: 8 LDS.64 transpose reads (every byte used), fused with
    //      the w8*X + w6*X^T fold and the column-sum (r2) partials.
    const float w8v = ws[8], w6v = ws[6];
    float r2a, r2b;
    {
        const float2* pa0 = P + (size_t)i1 * PSTRIDE + ib;        // col i1
        const float2* pb0 = P + (size_t)(i1 + 32) * PSTRIDE + ib; // col i1+32
        float2 q0 = pa0[0], q1 = pa0[1], q2 = pa0[2], q3 = pa0[3];
        r2a = ((q0.x + q1.x) + (q2.x + q3.x)) + ((q0.y + q1.y) + (q2.y + q3.y));
        va0.x = w8v*va0.x + w6v*q0.x;  va1.x = w8v*va1.x + w6v*q0.y;
        va0.y = w8v*va0.y + w6v*q1.x;  va1.y = w8v*va1.y + w6v*q1.y;
        va0.z = w8v*va0.z + w6v*q2.x;  va1.z = w8v*va1.z + w6v*q2.y;
        va0.w = w8v*va0.w + w6v*q3.x;  va1.w = w8v*va1.w + w6v*q3.y;
        q0 = pb0[0]; q1 = pb0[1]; q2 = pb0[2]; q3 = pb0[3];
        r2b = ((q0.x + q1.x) + (q2.x + q3.x)) + ((q0.y + q1.y) + (q2.y + q3.y));
        vb0.x = w8v*vb0.x + w6v*q0.x;  vb1.x = w8v*vb1.x + w6v*q0.y;
        vb0.y = w8v*vb0.y + w6v*q1.x;  vb1.y = w8v*vb1.y + w6v*q1.y;
        vb0.z = w8v*vb0.z + w6v*q2.x;  vb1.z = w8v*vb1.z + w6v*q2.y;
        vb0.w = w8v*vb0.w + w6v*q3.x;  vb1.w = w8v*vb1.w + w6v*q3.y;
    }
    // the 8 row-mates' chunks tile all 64 rows -> width-8 reduce = full column sums
    r2a += __shfl_xor_sync(0xffffffffu, r2a, 1, 8);
    r2a += __shfl_xor_sync(0xffffffffu, r2a, 2, 8);
    r2a += __shfl_xor_sync(0xffffffffu, r2a, 4, 8);
    r2b += __shfl_xor_sync(0xffffffffu, r2b, 1, 8);
    r2b += __shfl_xor_sync(0xffffffffu, r2b, 2, 8);
    r2b += __shfl_xor_sync(0xffffffffu, r2b, 4, 8);

    // weight folding (partition map from _set_partitions([0,1,2,3]) order)
    const float aA  = ws[12]*r1a + ws[13]*r2a + ws[3]*xa;     // row i1
    const float eA  = ws[5] *r1a + ws[9] *r2a + ws[0]*xa;
    const float aB  = ws[12]*r1b + ws[13]*r2b + ws[3]*xb;     // row i1+32
    const float eB  = ws[5] *r1b + ws[9] *r2b + ws[0]*xb;
    if (q == 0) {
        Cvec[i1]      = ws[7]*r1a + ws[10]*r2a + ws[1]*xa;
        Cvec[i1 + 32] = ws[7]*r1b + ws[10]*r2b + ws[1]*xb;
    }

    __syncthreads();                    // (2) Cvec ready

    // ---- Phase 3: close with T, D (float4 reads); emit 16 outputs.
    float T, D;
    {
        const float4 t0 = *(const float4*)Tw, t1 = *(const float4*)(Tw + 4);
        const float4 d0 = *(const float4*)Dw, d1 = *(const float4*)(Dw + 4);
        T = ((t0.x + t0.y) + (t0.z + t0.w)) + ((t1.x + t1.y) + (t1.z + t1.w));
        D = ((d0.x + d0.y) + (d0.z + d0.w)) + ((d1.x + d1.y) + (d1.z + d1.w));
    }
    const float gT = ws[14]*T + ws[4]*D;       // constant part
    const float gE = ws[11]*T + ws[2]*D;       // diagonal constant part
    const float cA = aA + gT, cB = aB + gT;
    const float evA = eA + gE, evB = eB + gE;

    const float4 c0 = *(const float4*)(Cvec + ib);
    const float4 c1 = *(const float4*)(Cvec + ib + 32);

    float4 oA0, oA1, oB0, oB1;
    oA0.x = cA + c0.x + va0.x;  oA0.y = cA + c0.y + va0.y;
    oA0.z = cA + c0.z + va0.z;  oA0.w = cA + c0.w + va0.w;
    oA1.x = cA + c1.x + va1.x;  oA1.y = cA + c1.y + va1.y;
    oA1.z = cA + c1.z + va1.z;  oA1.w = cA + c1.w + va1.w;
    oB0.x = cB + c0.x + vb0.x;  oB0.y = cB + c0.y + vb0.y;
    oB0.z = cB + c0.z + vb0.z;  oB0.w = cB + c0.w + vb0.w;
    oB1.x = cB + c1.x + vb1.x;  oB1.y = cB + c1.y + vb1.y;
    oB1.z = cB + c1.z + vb1.z;  oB1.w = cB + c1.w + vb1.w;

    // diagonal corrections: row i1 diag col i1 (low half); row i1+32 diag
    // col i1+32 (high half). Both land in the thread with ib == (i1 & ~3).
    const int dd = i1 - ib;
    if (dd >= 0 && dd < 4) {
        (&oA0.x)[dd] += evA;
        (&oB1.x)[dd] += evB;
    }

    float* orow = out + (size_t)b * 4096;
    *(float4*)(orow + i1 * 64 + ib)             = oA0;
    *(float4*)(orow + i1 * 64 + ib + 32)        = oA1;
    *(float4*)(orow + (i1 + 32) * 64 + ib)      = oB0;
    *(float4*)(orow + (i1 + 32) * 64 + ib + 32) = oB1;
}

extern "C" void kernel_launch(void* const* d_in, const int* in_sizes, int n_in,
                              void* d_out, int out_size)
{
    const float* X = (const float*)d_in[0];      // (1024, 4096) fp32
    const float* w = (const float*)d_in[1];      // (15,) fp32
    // d_in[2] = B (15,4096,4096) — unused: W is fully determined by w via the
    // partition-structure decomposition (validated R0-R10, rel_err ~4e-7).
    float* out = (float*)d_out;                  // (1024, 4096) fp32
    (void)in_sizes; (void)n_in; (void)out_size;

    sym_equiv_kernel<<<1024, THREADS>>>(X, w, out);
}